// round 9
// baseline (speedup 1.0000x reference)
#include <cuda_runtime.h>
#include <cuda_bf16.h>

#define NGRID   10000
#define NHALF   5000
#define NSTEPS  730
#define LENF    15
#define NEARZEROF 1e-5f
#define UNR     5

// 29.2 MB scratch for raw discharge q
__device__ float g_Q[(size_t)NSTEPS * NGRID];

// ---------------------------------------------------------------------------
// Kernel 1: sequential HBV scan, TWO cells per thread (ILP fills chain stalls)
// ---------------------------------------------------------------------------
__global__ __launch_bounds__(32, 1)
void hbv_scan_kernel(const float* __restrict__ x_phy,   // [NSTEPS, NGRID, 3]
                     const float* __restrict__ phy)     // [NGRID, 16]
{
    int tid = blockIdx.x * 32 + threadIdx.x;
    if (tid >= NHALF) return;
    int gg[2] = { tid, tid + NHALF };

    float BETA[2], FC[2], K0[2], K1[2], K2[2], LP[2], PERC[2], UZL[2],
          TT[2], CFMAX[2], CFR[2], CWH[2], BETAET[2], C[2];
    float invFC[2], invLPFC[2], CFRCFMAX[2];
    float snow[2], melt[2], sm[2], suz[2], slz[2], cslz[2], kcap[2];
    const float* xbase[2];
    float* qrow[2];

#pragma unroll
    for (int c = 0; c < 2; c++) {
        const float* ps = phy + gg[c] * 16;
        BETA[c]   = ps[0]  * 5.0f   + 1.0f;
        FC[c]     = ps[1]  * 950.0f + 50.0f;
        K0[c]     = ps[2]  * 0.85f  + 0.05f;
        K1[c]     = ps[3]  * 0.49f  + 0.01f;
        K2[c]     = ps[4]  * 0.199f + 0.001f;
        LP[c]     = ps[5]  * 0.8f   + 0.2f;
        PERC[c]   = ps[6]  * 10.0f;
        UZL[c]    = ps[7]  * 100.0f;
        TT[c]     = ps[8]  * 5.0f   - 2.5f;
        CFMAX[c]  = ps[9]  * 9.5f   + 0.5f;
        CFR[c]    = ps[10] * 0.1f;
        CWH[c]    = ps[11] * 0.2f;
        BETAET[c] = ps[12] * 4.7f   + 0.3f;
        C[c]      = ps[13];
        invFC[c]    = 1.0f / FC[c];
        invLPFC[c]  = 1.0f / (LP[c] * FC[c]);
        CFRCFMAX[c] = CFR[c] * CFMAX[c];
        snow[c] = NEARZEROF; melt[c] = NEARZEROF; sm[c] = NEARZEROF;
        suz[c]  = NEARZEROF; slz[c]  = NEARZEROF;
        cslz[c] = C[c] * slz[c];
        kcap[c] = cslz[c] * invFC[c];
        xbase[c] = x_phy + (size_t)gg[c] * 3;
        qrow[c]  = g_Q + gg[c];
    }

    const int rowstride = NGRID * 3;

    float Ap[2][UNR], Atm[2][UNR], Ape[2][UNR];
    float Bp[2][UNR], Btm[2][UNR], Bpe[2][UNR];

#define LOADG(P, T, E, GRP)                                               \
    _Pragma("unroll")                                                     \
    for (int c = 0; c < 2; c++) {                                         \
        _Pragma("unroll")                                                 \
        for (int u = 0; u < UNR; u++) {                                   \
            int idx = (GRP) * UNR + u;                                    \
            if (idx >= NSTEPS) idx = NSTEPS - 1;                          \
            const float* xn = xbase[c] + (size_t)idx * rowstride;         \
            P[c][u] = __ldg(xn + 0);                                      \
            T[c][u] = __ldg(xn + 1);                                      \
            E[c][u] = __ldg(xn + 2);                                      \
        }                                                                 \
    }

#define STEPS(P, T, E, BASE)                                              \
    _Pragma("unroll")                                                     \
    for (int u = 0; u < UNR; u++) {                                       \
        _Pragma("unroll")                                                 \
        for (int c = 0; c < 2; c++) {                                     \
            float p  = P[c][u];                                           \
            float tm = T[c][u];                                           \
            float pe = E[c][u];                                           \
            float rain     = (tm >= TT[c]) ? p : 0.0f;                    \
            float snowfall = p - rain;                                    \
            float mpot     = fmaxf(CFMAX[c]    * (tm - TT[c]), 0.0f);     \
            float rpot     = fmaxf(CFRCFMAX[c] * (TT[c] - tm), 0.0f);     \
            float soil_wet = fminf(__powf(sm[c] * invFC[c], BETA[c]), 1.0f); \
            float sp     = snow[c] + snowfall;                            \
            float snow1  = fmaxf(sp - mpot, 0.0f);                        \
            float m      = sp - snow1;                                    \
            float melt1  = melt[c] + m;                                   \
            float melt2  = fmaxf(melt1 - rpot, 0.0f);                     \
            float refr   = melt1 - melt2;                                 \
            snow[c]      = snow1 + refr;                                  \
            float tosoil = fmaxf(melt2 - CWH[c] * snow[c], 0.0f);         \
            melt[c]      = melt2 - tosoil;                                \
            float rt       = rain + tosoil;                               \
            float recharge = rt * soil_wet;                               \
            float sm_pre   = fmaf(rt, 1.0f - soil_wet, sm[c]);            \
            float sm_c     = fminf(sm_pre, FC[c]);                        \
            float excess   = sm_pre - sm_c;                               \
            float evapfac  = fminf(__powf(sm_pre * invLPFC[c], BETAET[c]), 1.0f); \
            float sm_et    = fmaxf(fmaf(-pe, evapfac, sm_c), NEARZEROF);  \
            float cap      = fminf(slz[c], fmaf(-kcap[c], sm_et, cslz[c])); \
            sm[c]          = fmaxf(sm_et + cap, NEARZEROF);               \
            slz[c]         = fmaxf(slz[c] - cap, NEARZEROF);              \
            suz[c] += recharge + excess;                                  \
            float percact = fminf(suz[c], PERC[c]);                       \
            suz[c] -= percact;                                            \
            float q0 = K0[c] * fmaxf(suz[c] - UZL[c], 0.0f);              \
            suz[c] -= q0;                                                 \
            float q1 = K1[c] * suz[c];                                    \
            suz[c] -= q1;                                                 \
            slz[c] += percact;                                            \
            float q2 = K2[c] * slz[c];                                    \
            slz[c] -= q2;                                                 \
            cslz[c] = C[c] * slz[c];                                      \
            kcap[c] = cslz[c] * invFC[c];                                 \
            qrow[c][(size_t)((BASE) + u) * NGRID] = q0 + q1 + q2;         \
        }                                                                 \
    }

    LOADG(Ap, Atm, Ape, 0)
    LOADG(Bp, Btm, Bpe, 1)

    for (int base = 0; base < NSTEPS; base += 2 * UNR) {
        int grp = base / UNR;
        STEPS(Ap, Atm, Ape, base)
        LOADG(Ap, Atm, Ape, grp + 2)
        STEPS(Bp, Btm, Bpe, base + UNR)
        LOADG(Bp, Btm, Bpe, grp + 3)
    }
#undef LOADG
#undef STEPS
}

// ---------------------------------------------------------------------------
// Kernel 2: gamma routing, staged register prefetch (chunks of 15).
// ---------------------------------------------------------------------------
#define TTILE 75
#define NCHUNK (TTILE / LENF)   // 5

__global__ __launch_bounds__(128, 1)
void hbv_rout_kernel(const float* __restrict__ phy,   // [NGRID, 16]
                     float* __restrict__ out)         // [NSTEPS, NGRID]
{
    int g = blockIdx.x * blockDim.x + threadIdx.x;
    if (g >= NGRID) return;

    // ln(k + 0.5), k = 0..14
    const float LOGTG[LENF] = {
        -0.69314718f, 0.40546511f, 0.91629073f, 1.25276297f, 1.50407740f,
         1.70474809f, 1.87180218f, 2.01490302f, 2.14006616f, 2.25129180f,
         2.35137526f, 2.44234704f, 2.52572864f, 2.60268969f, 2.67418505f };

    float aa    = fmaxf(phy[g * 16 + 14] * 2.9f, 0.0f) + 0.1f;
    float theta = fmaxf(phy[g * 16 + 15] * 6.5f, 0.0f) + 0.5f;
    float invTheta = 1.0f / theta;
    float am1 = aa - 1.0f;

    float w[LENF];
    float wsum = 0.0f;
#pragma unroll
    for (int k = 0; k < LENF; k++) {
        float tg = (float)k + 0.5f;
        float e = expf(fmaf(am1, LOGTG[k], -tg * invTheta));
        w[k] = e;
        wsum += e;
    }
    float invw = 1.0f / wsum;
#pragma unroll
    for (int k = 0; k < LENF; k++) w[k] *= invw;

    int t0 = blockIdx.y * TTILE;          // multiple of 15
    const float* qcol = g_Q + g;
    float* ocol = out + g;

    // circular history: h[tau % 15] holds Q[tau]; t0 % 15 == 0.
    float h[LENF];
#pragma unroll
    for (int j = 0; j < LENF - 1; j++) {
        int t = t0 - (LENF - 1) + j;      // slot (t % 15) = j+1
        h[j + 1] = (t >= 0) ? __ldg(qcol + (size_t)t * NGRID) : 0.0f;
    }
    h[0] = 0.0f;

    // batched preload of chunk 0 (MLP = 15)
    float buf[LENF], nxt[LENF];
#pragma unroll
    for (int i = 0; i < LENF; i++) {
        int t = t0 + i;
        if (t > NSTEPS - 1) t = NSTEPS - 1;
        buf[i] = __ldg(qcol + (size_t)t * NGRID);
    }

#pragma unroll
    for (int ch = 0; ch < NCHUNK; ch++) {
        // prefetch chunk ch+1 (clamped; overlaps with compute below)
#pragma unroll
        for (int i = 0; i < LENF; i++) {
            int t = t0 + (ch + 1) * LENF + i;
            if (t > NSTEPS - 1) t = NSTEPS - 1;
            nxt[i] = __ldg(qcol + (size_t)t * NGRID);
        }
        // compute 15 outputs; slot of (t0+ch*15+i) is i
#pragma unroll
        for (int i = 0; i < LENF; i++) {
            h[i] = buf[i];
            float qr = 0.0f;
#pragma unroll
            for (int k = 0; k < LENF; k++) {
                qr = fmaf(w[k], h[(i - k + LENF) % LENF], qr);
            }
            int t = t0 + ch * LENF + i;
            if (t < NSTEPS) ocol[(size_t)t * NGRID] = qr;
        }
#pragma unroll
        for (int i = 0; i < LENF; i++) buf[i] = nxt[i];
    }
}

extern "C" void kernel_launch(void* const* d_in, const int* in_sizes, int n_in,
                              void* d_out, int out_size) {
    const float* x_phy = (const float*)d_in[0];
    const float* phy   = (const float*)d_in[1];
    float* out         = (float*)d_out;
    (void)in_sizes; (void)n_in; (void)out_size;

    // scan: 2 cells/thread, 32-thread blocks -> 157 blocks over 148 SMs
    hbv_scan_kernel<<<(NHALF + 31) / 32, 32>>>(x_phy, phy);

    // routing: (g-tiles, t-tiles)
    dim3 rgrid((NGRID + 127) / 128, (NSTEPS + TTILE - 1) / TTILE);
    hbv_rout_kernel<<<rgrid, 128>>>(phy, out);
}

// round 10
// speedup vs baseline: 1.2907x; 1.2907x over previous
#include <cuda_runtime.h>
#include <cuda_bf16.h>

#define NGRID   10000
#define NSTEPS  730
#define LENF    15
#define NEARZEROF 1e-5f
#define UNR     5          // 730 % 10 == 0 (ping-pong pairs)

// 29.2 MB scratch for raw discharge q
__device__ float g_Q[(size_t)NSTEPS * NGRID];

__device__ __forceinline__ float fast_lg2(float x) {
    float r; asm("lg2.approx.f32 %0, %1;" : "=f"(r) : "f"(x)); return r;
}
__device__ __forceinline__ float fast_ex2(float x) {
    float r; asm("ex2.approx.f32 %0, %1;" : "=f"(r) : "f"(x)); return r;
}

// ---------------------------------------------------------------------------
// Kernel 1: sequential HBV scan, one thread per cell, chain-optimized.
// ---------------------------------------------------------------------------
__global__ __launch_bounds__(64, 1)
void hbv_scan_kernel(const float* __restrict__ x_phy,   // [NSTEPS, NGRID, 3]
                     const float* __restrict__ phy)     // [NGRID, 16]
{
    int g = blockIdx.x * blockDim.x + threadIdx.x;
    if (g >= NGRID) return;

    const float* ps = phy + g * 16;
    float BETA   = ps[0]  * 5.0f   + 1.0f;
    float FC     = ps[1]  * 950.0f + 50.0f;
    float K0     = ps[2]  * 0.85f  + 0.05f;
    float K1     = ps[3]  * 0.49f  + 0.01f;
    float K2     = ps[4]  * 0.199f + 0.001f;
    float LP     = ps[5]  * 0.8f   + 0.2f;
    float PERC   = ps[6]  * 10.0f;
    float UZL    = ps[7]  * 100.0f;
    float TT     = ps[8]  * 5.0f   - 2.5f;
    float CFMAX  = ps[9]  * 9.5f   + 0.5f;
    float CFR    = ps[10] * 0.1f;
    float CWH    = ps[11] * 0.2f;
    float BETAET = ps[12] * 4.7f   + 0.3f;
    float C      = ps[13];

    float invFC    = 1.0f / FC;
    float invLPFC  = 1.0f / (LP * FC);
    float CFRCFMAX = CFR * CFMAX;
    // folded log constants: pow(x*c, b) = ex2(b*lg2(x) + b*log2(c))
    float CA = BETA   * fast_lg2(invFC);    // soil_wet offset
    float CE = BETAET * fast_lg2(invLPFC);  // evapfac offset

    float snow = NEARZEROF, melt = NEARZEROF, sm = NEARZEROF,
          suz = NEARZEROF, slz = NEARZEROF;
    float cslz    = C * slz;                // off-chain capillary precomputes
    float om_kcap = 1.0f - cslz * invFC;

    const int rowstride = NGRID * 3;
    const float* xbase = x_phy + (size_t)g * 3;
    float* qrow = g_Q + g;

    float Ap[UNR], Atm[UNR], Ape[UNR];
    float Bp[UNR], Btm[UNR], Bpe[UNR];

#define LOADG(P, T, E, GRP)                                             \
    _Pragma("unroll")                                                   \
    for (int u = 0; u < UNR; u++) {                                     \
        int idx = (GRP) * UNR + u;                                      \
        if (idx >= NSTEPS) idx = NSTEPS - 1;                            \
        const float* xn = xbase + (size_t)idx * rowstride;              \
        P[u] = __ldg(xn + 0); T[u] = __ldg(xn + 1); E[u] = __ldg(xn + 2); \
    }

#define STEPS(P, T, E, BASE)                                            \
    _Pragma("unroll")                                                   \
    for (int u = 0; u < UNR; u++) {                                     \
        float p  = P[u];                                                \
        float tm = T[u];                                                \
        float pe = E[u];                                                \
        /* input-only precomputes (off the carried chain) */            \
        float rain     = (tm >= TT) ? p : 0.0f;                         \
        float snowfall = p - rain;                                      \
        float mpot     = fmaxf(CFMAX    * (tm - TT), 0.0f);             \
        float rpot     = fmaxf(CFRCFMAX * (TT - tm), 0.0f);             \
        /* soil_wet: ex2(fma(B, lg2(sm), CA)) — folded constant */      \
        float soil_wet = fminf(fast_ex2(fmaf(BETA, fast_lg2(sm), CA)), 1.0f); \
        /* snow bucket (parallel chain) */                              \
        float sp     = snow + snowfall;                                 \
        float snow1  = fmaxf(sp - mpot, 0.0f);                          \
        float m      = sp - snow1;                                      \
        float melt1  = melt + m;                                        \
        float melt2  = fmaxf(melt1 - rpot, 0.0f);                       \
        float refr   = melt1 - melt2;                                   \
        snow         = snow1 + refr;                                    \
        float tosoil = fmaxf(melt2 - CWH * snow, 0.0f);                 \
        melt         = melt2 - tosoil;                                  \
        /* soil bucket (chain-shortened, exact) */                      \
        float rt       = rain + tosoil;                                 \
        float smrt     = sm + rt;            /* parallel to soil_wet */ \
        float recharge = rt * soil_wet;      /* off-chain (suz)      */ \
        float sm_pre   = fmaf(-rt, soil_wet, smrt);                     \
        float sm_c     = fminf(sm_pre, FC);                             \
        float excess   = sm_pre - sm_c;      /* off-chain (suz)      */ \
        float evapfac  = fminf(fast_ex2(fmaf(BETAET, fast_lg2(sm_pre), CE)), 1.0f); \
        float sm_et    = fmaxf(fmaf(-pe, evapfac, sm_c), NEARZEROF);    \
        /* cap >= 0 always, so sm = sm_et + cap, no clamp needed:   */  \
        /* sm = min(sm_et + slz, sm_et*(1-kcap) + cslz)             */  \
        float sm_a     = fmaf(sm_et, om_kcap, cslz);                    \
        float sm_b     = sm_et + slz;                                   \
        sm             = fminf(sm_a, sm_b);                             \
        float cap      = sm - sm_et;         /* off sm critical path */ \
        slz            = fmaxf(slz - cap, NEARZEROF);                   \
        /* response routine (suz/slz chains, off sm path) */            \
        suz += recharge + excess;                                       \
        float percact = fminf(suz, PERC);                               \
        suz -= percact;                                                 \
        float q0 = K0 * fmaxf(suz - UZL, 0.0f);                         \
        suz -= q0;                                                      \
        float q1 = K1 * suz;                                            \
        suz -= q1;                                                      \
        slz += percact;                                                 \
        float q2 = K2 * slz;                                            \
        slz -= q2;                                                      \
        cslz    = C * slz;                                              \
        om_kcap = 1.0f - cslz * invFC;                                  \
        qrow[(size_t)((BASE) + u) * NGRID] = q0 + q1 + q2;              \
    }

    LOADG(Ap, Atm, Ape, 0)
    LOADG(Bp, Btm, Bpe, 1)

    for (int base = 0; base < NSTEPS; base += 2 * UNR) {
        int grp = base / UNR;
        STEPS(Ap, Atm, Ape, base)
        LOADG(Ap, Atm, Ape, grp + 2)
        STEPS(Bp, Btm, Bpe, base + UNR)
        LOADG(Bp, Btm, Bpe, grp + 3)
    }
#undef LOADG
#undef STEPS
}

// ---------------------------------------------------------------------------
// Kernel 2: gamma routing, staged register prefetch (chunks of 15).
// ---------------------------------------------------------------------------
#define TTILE 75
#define NCHUNK (TTILE / LENF)   // 5

__global__ __launch_bounds__(128, 1)
void hbv_rout_kernel(const float* __restrict__ phy,   // [NGRID, 16]
                     float* __restrict__ out)         // [NSTEPS, NGRID]
{
    int g = blockIdx.x * blockDim.x + threadIdx.x;
    if (g >= NGRID) return;

    // ln(k + 0.5), k = 0..14
    const float LOGTG[LENF] = {
        -0.69314718f, 0.40546511f, 0.91629073f, 1.25276297f, 1.50407740f,
         1.70474809f, 1.87180218f, 2.01490302f, 2.14006616f, 2.25129180f,
         2.35137526f, 2.44234704f, 2.52572864f, 2.60268969f, 2.67418505f };

    float aa    = fmaxf(phy[g * 16 + 14] * 2.9f, 0.0f) + 0.1f;
    float theta = fmaxf(phy[g * 16 + 15] * 6.5f, 0.0f) + 0.5f;
    float invTheta = 1.0f / theta;
    float am1 = aa - 1.0f;

    float w[LENF];
    float wsum = 0.0f;
#pragma unroll
    for (int k = 0; k < LENF; k++) {
        float tg = (float)k + 0.5f;
        float e = expf(fmaf(am1, LOGTG[k], -tg * invTheta));
        w[k] = e;
        wsum += e;
    }
    float invw = 1.0f / wsum;
#pragma unroll
    for (int k = 0; k < LENF; k++) w[k] *= invw;

    int t0 = blockIdx.y * TTILE;          // multiple of 15
    const float* qcol = g_Q + g;
    float* ocol = out + g;

    // circular history: h[tau % 15] holds Q[tau]; t0 % 15 == 0.
    float h[LENF];
#pragma unroll
    for (int j = 0; j < LENF - 1; j++) {
        int t = t0 - (LENF - 1) + j;      // slot (t % 15) = j+1
        h[j + 1] = (t >= 0) ? __ldg(qcol + (size_t)t * NGRID) : 0.0f;
    }
    h[0] = 0.0f;

    // batched preload of chunk 0 (MLP = 15)
    float buf[LENF], nxt[LENF];
#pragma unroll
    for (int i = 0; i < LENF; i++) {
        int t = t0 + i;
        if (t > NSTEPS - 1) t = NSTEPS - 1;
        buf[i] = __ldg(qcol + (size_t)t * NGRID);
    }

#pragma unroll
    for (int ch = 0; ch < NCHUNK; ch++) {
        // prefetch chunk ch+1 (clamped; overlaps compute)
#pragma unroll
        for (int i = 0; i < LENF; i++) {
            int t = t0 + (ch + 1) * LENF + i;
            if (t > NSTEPS - 1) t = NSTEPS - 1;
            nxt[i] = __ldg(qcol + (size_t)t * NGRID);
        }
        // compute 15 outputs; slot of (t0+ch*15+i) is i
#pragma unroll
        for (int i = 0; i < LENF; i++) {
            h[i] = buf[i];
            float qr = 0.0f;
#pragma unroll
            for (int k = 0; k < LENF; k++) {
                qr = fmaf(w[k], h[(i - k + LENF) % LENF], qr);
            }
            int t = t0 + ch * LENF + i;
            if (t < NSTEPS) ocol[(size_t)t * NGRID] = qr;
        }
#pragma unroll
        for (int i = 0; i < LENF; i++) buf[i] = nxt[i];
    }
}

extern "C" void kernel_launch(void* const* d_in, const int* in_sizes, int n_in,
                              void* d_out, int out_size) {
    const float* x_phy = (const float*)d_in[0];
    const float* phy   = (const float*)d_in[1];
    float* out         = (float*)d_out;
    (void)in_sizes; (void)n_in; (void)out_size;

    // scan: 1 cell/thread, 64-thread blocks -> 157 blocks over 148 SMs
    hbv_scan_kernel<<<(NGRID + 63) / 64, 64>>>(x_phy, phy);

    // routing: (g-tiles, t-tiles)
    dim3 rgrid((NGRID + 127) / 128, (NSTEPS + TTILE - 1) / TTILE);
    hbv_rout_kernel<<<rgrid, 128>>>(phy, out);
}